// round 1
// baseline (speedup 1.0000x reference)
#include <cuda_runtime.h>

#define BB 128
#define LL 200
#define HH 128
#define CC 64

// ---- scratch (static device globals; no allocations) ----
__device__ float g_K [BB*LL*CC];   // softmaxed keys      (b,l,c)
__device__ float g_Qp[BB*LL*HH];   // Qe@W1q.T + b1       (b,l,h)
__device__ float g_E [BB*LL*HH];   // sigmoid erase gate  (b,l,h)
__device__ float g_A [BB*LL*HH];   // tanh add vector     (b,l,h)
__device__ float g_R [BB*LL*HH];   // K_t . M_{t-1}       (b,l,h)

// 32-row x 64-col register-tiled dot over 128, inputs in smem (stride 129)
__device__ __forceinline__ void tile_dot(const float* __restrict__ qb,
                                         const float* __restrict__ wb,
                                         float acc[4][4])
{
    #pragma unroll
    for (int r = 0; r < 4; ++r)
        #pragma unroll
        for (int k = 0; k < 4; ++k) acc[r][k] = 0.f;

    #pragma unroll 4
    for (int j = 0; j < 128; ++j) {
        float q0 = qb[0*129 + j];
        float q1 = qb[1*129 + j];
        float q2 = qb[2*129 + j];
        float q3 = qb[3*129 + j];
        #pragma unroll
        for (int k = 0; k < 4; ++k) {
            float wv = wb[k*129 + j];
            acc[0][k] = fmaf(q0, wv, acc[0][k]);
            acc[1][k] = fmaf(q1, wv, acc[1][k]);
            acc[2][k] = fmaf(q2, wv, acc[2][k]);
            acc[3][k] = fmaf(q3, wv, acc[3][k]);
        }
    }
}

// ---------------- Kernel 1: K = softmax(Qe@key_W.T), Qproj = Qe@W1q.T + b1 ----
extern "C" __global__ void __launch_bounds__(128)
k_pre_qk(const int* __restrict__ Q, const float* __restrict__ q_emb,
         const float* __restrict__ key_W, const float* __restrict__ p_W1,
         const float* __restrict__ p_b1)
{
    extern __shared__ float sm[];
    float* sQe = sm;              // 32*129
    float* sW  = sm + 32*129;     // up to 128*129
    __shared__ int sQidx[32];

    const int tid  = threadIdx.x;
    const int row0 = blockIdx.x * 32;

    if (tid < 32) sQidx[tid] = Q[row0 + tid];
    __syncthreads();

    for (int idx = tid; idx < 32*128; idx += 128) {
        int r = idx >> 7, j = idx & 127;
        sQe[r*129 + j] = q_emb[sQidx[r]*128 + j];
    }
    for (int idx = tid; idx < 64*128; idx += 128) {
        int r = idx >> 7, j = idx & 127;
        sW[r*129 + j] = key_W[idx];
    }
    __syncthreads();

    const int cg = tid & 15;      // 16 col-groups (x4 cols)
    const int rg = tid >> 4;      // 8 row-groups  (x4 rows)
    float acc[4][4];

    // ---- logits (32x64) + softmax over c ----
    tile_dot(sQe + rg*4*129, sW + cg*4*129, acc);
    __syncthreads();              // done reading key_W; safe to overwrite sW below

    #pragma unroll
    for (int r = 0; r < 4; ++r) {
        float mx = fmaxf(fmaxf(acc[r][0], acc[r][1]), fmaxf(acc[r][2], acc[r][3]));
        #pragma unroll
        for (int off = 8; off >= 1; off >>= 1)
            mx = fmaxf(mx, __shfl_xor_sync(0xffffffffu, mx, off));
        float e0 = __expf(acc[r][0] - mx);
        float e1 = __expf(acc[r][1] - mx);
        float e2 = __expf(acc[r][2] - mx);
        float e3 = __expf(acc[r][3] - mx);
        float sum = (e0 + e1) + (e2 + e3);
        #pragma unroll
        for (int off = 8; off >= 1; off >>= 1)
            sum += __shfl_xor_sync(0xffffffffu, sum, off);
        float inv = __frcp_rn(sum);
        float4 o = make_float4(e0*inv, e1*inv, e2*inv, e3*inv);
        *(float4*)&g_K[(row0 + rg*4 + r)*CC + cg*4] = o;
    }

    // ---- Qproj: load W1q = p_W1[:, :128] ----
    for (int idx = tid; idx < 128*128; idx += 128) {
        int r = idx >> 7, j = idx & 127;
        sW[r*129 + j] = p_W1[r*256 + j];
    }
    __syncthreads();

    #pragma unroll
    for (int chunk = 0; chunk < 2; ++chunk) {
        const int col0 = chunk * 64;
        tile_dot(sQe + rg*4*129, sW + (col0 + cg*4)*129, acc);
        #pragma unroll
        for (int r = 0; r < 4; ++r) {
            int row = row0 + rg*4 + r;
            int col = col0 + cg*4;
            float4 o = make_float4(acc[r][0] + p_b1[col+0],
                                   acc[r][1] + p_b1[col+1],
                                   acc[r][2] + p_b1[col+2],
                                   acc[r][3] + p_b1[col+3]);
            *(float4*)&g_Qp[row*HH + col] = o;
        }
    }
}

// ---------------- Kernel 2: E = sigmoid(Xe@e_W.T+b), A = tanh(Xe@a_W.T+b) ----
extern "C" __global__ void __launch_bounds__(128)
k_pre_ea(const int* __restrict__ X, const float* __restrict__ x_emb,
         const float* __restrict__ e_W, const float* __restrict__ e_b,
         const float* __restrict__ a_W, const float* __restrict__ a_b)
{
    extern __shared__ float sm[];
    float* sXe = sm;
    float* sW  = sm + 32*129;
    __shared__ int sXidx[32];

    const int tid  = threadIdx.x;
    const int row0 = blockIdx.x * 32;

    if (tid < 32) sXidx[tid] = X[row0 + tid];
    __syncthreads();

    for (int idx = tid; idx < 32*128; idx += 128) {
        int r = idx >> 7, j = idx & 127;
        sXe[r*129 + j] = x_emb[sXidx[r]*128 + j];
    }
    for (int idx = tid; idx < 128*128; idx += 128) {
        int r = idx >> 7, j = idx & 127;
        sW[r*129 + j] = e_W[idx];
    }
    __syncthreads();

    const int cg = tid & 15;
    const int rg = tid >> 4;
    float acc[4][4];

    // E chunks
    #pragma unroll
    for (int chunk = 0; chunk < 2; ++chunk) {
        const int col0 = chunk * 64;
        tile_dot(sXe + rg*4*129, sW + (col0 + cg*4)*129, acc);
        #pragma unroll
        for (int r = 0; r < 4; ++r) {
            int row = row0 + rg*4 + r;
            int col = col0 + cg*4;
            float4 o;
            o.x = 1.f/(1.f + __expf(-(acc[r][0] + e_b[col+0])));
            o.y = 1.f/(1.f + __expf(-(acc[r][1] + e_b[col+1])));
            o.z = 1.f/(1.f + __expf(-(acc[r][2] + e_b[col+2])));
            o.w = 1.f/(1.f + __expf(-(acc[r][3] + e_b[col+3])));
            *(float4*)&g_E[row*HH + col] = o;
        }
    }
    __syncthreads();
    for (int idx = tid; idx < 128*128; idx += 128) {
        int r = idx >> 7, j = idx & 127;
        sW[r*129 + j] = a_W[idx];
    }
    __syncthreads();

    // A chunks
    #pragma unroll
    for (int chunk = 0; chunk < 2; ++chunk) {
        const int col0 = chunk * 64;
        tile_dot(sXe + rg*4*129, sW + (col0 + cg*4)*129, acc);
        #pragma unroll
        for (int r = 0; r < 4; ++r) {
            int row = row0 + rg*4 + r;
            int col = col0 + cg*4;
            float4 o;
            o.x = tanhf(acc[r][0] + a_b[col+0]);
            o.y = tanhf(acc[r][1] + a_b[col+1]);
            o.z = tanhf(acc[r][2] + a_b[col+2]);
            o.w = tanhf(acc[r][3] + a_b[col+3]);
            *(float4*)&g_A[row*HH + col] = o;
        }
    }
}

// ---------------- Kernel 3: the scan, fully parallel over (b,c,h) -------------
// warp = (b, 8 h's); lane: sub=lane>>2 picks h, g=lane&3 picks 16-wide c slice.
// m lives in registers; R_t uses m BEFORE the update (M0 = 0).
extern "C" __global__ void __launch_bounds__(256)
k_scan()
{
    const int tid  = threadIdx.x;
    const int b    = blockIdx.x >> 1;
    const int hblk = blockIdx.x & 1;
    const int wid  = tid >> 5;
    const int lane = tid & 31;
    const int sub  = lane >> 2;
    const int g    = lane & 3;
    const int h    = hblk*64 + wid*8 + sub;

    const float* Kp = g_K + b*LL*CC + g*16;
    const float* Ep = g_E + b*LL*HH + h;
    const float* Ap = g_A + b*LL*HH + h;
    float*       Rp = g_R + b*LL*HH + h;

    float m[16];
    #pragma unroll
    for (int j = 0; j < 16; ++j) m[j] = 0.f;

    #pragma unroll 2
    for (int t = 0; t < LL; ++t) {
        float k[16];
        *(float4*)&k[0]  = *(const float4*)(Kp + 0);
        *(float4*)&k[4]  = *(const float4*)(Kp + 4);
        *(float4*)&k[8]  = *(const float4*)(Kp + 8);
        *(float4*)&k[12] = *(const float4*)(Kp + 12);
        float e = *Ep;
        float a = *Ap;

        float s0 = 0.f, s1 = 0.f, s2 = 0.f, s3 = 0.f;
        #pragma unroll
        for (int j = 0; j < 4; ++j) {
            s0 = fmaf(k[j+ 0], m[j+ 0], s0);
            s1 = fmaf(k[j+ 4], m[j+ 4], s1);
            s2 = fmaf(k[j+ 8], m[j+ 8], s2);
            s3 = fmaf(k[j+12], m[j+12], s3);
        }
        float s = (s0 + s1) + (s2 + s3);
        s += __shfl_xor_sync(0xffffffffu, s, 1);
        s += __shfl_xor_sync(0xffffffffu, s, 2);
        if (g == 0) *Rp = s;

        #pragma unroll
        for (int j = 0; j < 16; ++j) {
            float tmp = fmaf(m[j], -e, a);     // a - m*e
            m[j] = fmaf(k[j], tmp, m[j]);      // m*(1-k*e) + k*a
        }
        Kp += CC; Ep += HH; Ap += HH; Rp += HH;
    }
}

// ---------------- Kernel 4: P = sigmoid(tanh(Qp + R@W1r.T) . pW2 + b2) --------
extern "C" __global__ void __launch_bounds__(128)
k_out(const float* __restrict__ p_W1, const float* __restrict__ p_W2,
      const float* __restrict__ p_b2, float* __restrict__ out)
{
    extern __shared__ float sm[];
    float* sR  = sm;                // 32*129
    float* sQp = sm + 32*129;       // 32*129
    float* sW  = sm + 2*32*129;     // 128*129 (W1r)
    __shared__ float sP[32];
    __shared__ float sW2[128];

    const int tid  = threadIdx.x;
    const int row0 = blockIdx.x * 32;

    if (tid < 32) sP[tid] = 0.f;
    sW2[tid] = p_W2[tid];

    for (int idx = tid; idx < 32*128; idx += 128) {
        int r = idx >> 7, j = idx & 127;
        sR [r*129 + j] = g_R [(row0 + r)*HH + j];
        sQp[r*129 + j] = g_Qp[(row0 + r)*HH + j];
    }
    for (int idx = tid; idx < 128*128; idx += 128) {
        int r = idx >> 7, j = idx & 127;
        sW[r*129 + j] = p_W1[r*256 + 128 + j];   // W1r = p_W1[:,128:]
    }
    __syncthreads();

    const int cg = tid & 15;
    const int rg = tid >> 4;
    float acc[4][4];
    float psum[4] = {0.f, 0.f, 0.f, 0.f};

    #pragma unroll
    for (int chunk = 0; chunk < 2; ++chunk) {
        const int col0 = chunk * 64;
        tile_dot(sR + rg*4*129, sW + (col0 + cg*4)*129, acc);
        #pragma unroll
        for (int r = 0; r < 4; ++r) {
            #pragma unroll
            for (int k = 0; k < 4; ++k) {
                int col = col0 + cg*4 + k;
                float hv = tanhf(acc[r][k] + sQp[(rg*4 + r)*129 + col]);
                psum[r] = fmaf(hv, sW2[col], psum[r]);
            }
        }
    }
    #pragma unroll
    for (int r = 0; r < 4; ++r) atomicAdd(&sP[rg*4 + r], psum[r]);
    __syncthreads();

    if (tid < 32) {
        float x = sP[tid] + p_b2[0];
        out[row0 + tid] = 1.f/(1.f + __expf(-x));
    }
}

// ---------------- launch ----------------
extern "C" void kernel_launch(void* const* d_in, const int* in_sizes, int n_in,
                              void* d_out, int out_size)
{
    const int*   X     = (const int*)  d_in[0];
    const int*   Q     = (const int*)  d_in[1];
    const float* q_emb = (const float*)d_in[2];
    const float* x_emb = (const float*)d_in[3];
    const float* key_W = (const float*)d_in[4];
    const float* p_W1  = (const float*)d_in[5];
    const float* p_b1  = (const float*)d_in[6];
    const float* p_W2  = (const float*)d_in[7];
    const float* p_b2  = (const float*)d_in[8];
    const float* e_W   = (const float*)d_in[9];
    const float* e_b   = (const float*)d_in[10];
    const float* a_W   = (const float*)d_in[11];
    const float* a_b   = (const float*)d_in[12];
    float* out = (float*)d_out;

    const int smem12 = (32*129 + 128*129) * 4;        // 82.6 KB
    const int smem4  = (2*32*129 + 128*129) * 4;      // 99.1 KB
    cudaFuncSetAttribute(k_pre_qk, cudaFuncAttributeMaxDynamicSharedMemorySize, smem12);
    cudaFuncSetAttribute(k_pre_ea, cudaFuncAttributeMaxDynamicSharedMemorySize, smem12);
    cudaFuncSetAttribute(k_out,    cudaFuncAttributeMaxDynamicSharedMemorySize, smem4);

    k_pre_qk<<<(BB*LL)/32, 128, smem12>>>(Q, q_emb, key_W, p_W1, p_b1);
    k_pre_ea<<<(BB*LL)/32, 128, smem12>>>(X, x_emb, e_W, e_b, a_W, a_b);
    k_scan  <<<BB*2, 256>>>();
    k_out   <<<(BB*LL)/32, 128, smem4>>>(p_W1, p_W2, p_b2, out);
}

// round 2
// speedup vs baseline: 1.2780x; 1.2780x over previous
#include <cuda_runtime.h>

#define BB 128
#define LL 200
#define HH 128
#define CC 64

#define IS 132            // smem row stride (floats) for 128-wide rows
#define NROWS 64          // rows per block
#define SM_IN  (NROWS*IS)         // 8448 floats
#define SM_W   (HH*IS)            // 16896 floats
#define SMEM_BYTES ((SM_IN + SM_W) * 4)

// ---- scratch (static device globals; no allocations) ----
__device__ float g_K [BB*LL*CC];   // softmaxed keys      (b,l,c)
__device__ float g_Qp[BB*LL*HH];   // Qe@W1q.T + b1       (b,l,h)
__device__ float g_E [BB*LL*HH];   // sigmoid erase gate  (b,l,h)
__device__ float g_A [BB*LL*HH];   // tanh add vector     (b,l,h)
__device__ float g_R [BB*LL*HH];   // K_t . M_{t-1}       (b,l,h)

__device__ __forceinline__ float fast_tanh(float x) {
    float y; asm("tanh.approx.f32 %0, %1;" : "=f"(y) : "f"(x)); return y;
}
__device__ __forceinline__ float fast_sigmoid(float x) {
    return 1.f / (1.f + __expf(-x));
}

// 64-row x 128-col GEMM core: thread tile 8 rows x 4 cols, K=128, j by float4.
// cx = tid&31 (col group), ry = tid>>5 (warp = row group of 8).
// q loads: warp-broadcast. w loads: conflict-free (stride 132).
__device__ __forceinline__ void gemm_8x4(const float* __restrict__ sIn,
                                         const float* __restrict__ sW,
                                         int ry, int c0, float acc[8][4])
{
    #pragma unroll
    for (int r = 0; r < 8; ++r)
        #pragma unroll
        for (int k = 0; k < 4; ++k) acc[r][k] = 0.f;

    #pragma unroll 2
    for (int j0 = 0; j0 < 128; j0 += 4) {
        float4 q[8], w[4];
        #pragma unroll
        for (int r = 0; r < 8; ++r)
            q[r] = *(const float4*)&sIn[(ry*8 + r)*IS + j0];
        #pragma unroll
        for (int k = 0; k < 4; ++k)
            w[k] = *(const float4*)&sW[(c0 + k)*IS + j0];
        #pragma unroll
        for (int r = 0; r < 8; ++r)
            #pragma unroll
            for (int k = 0; k < 4; ++k) {
                acc[r][k] = fmaf(q[r].x, w[k].x, acc[r][k]);
                acc[r][k] = fmaf(q[r].y, w[k].y, acc[r][k]);
                acc[r][k] = fmaf(q[r].z, w[k].z, acc[r][k]);
                acc[r][k] = fmaf(q[r].w, w[k].w, acc[r][k]);
            }
    }
}

// ---------------- Kernel 1: fused precompute ---------------------------------
// blocks [0,400):  K = softmax(Qe@key_W.T), Qproj = Qe@W1q.T + b1
// blocks [400,800): E = sigmoid(Xe@e_W.T+b), A = tanh(Xe@a_W.T+b)
extern "C" __global__ void __launch_bounds__(256, 2)
k_pre(const int* __restrict__ X, const int* __restrict__ Q,
      const float* __restrict__ q_emb, const float* __restrict__ x_emb,
      const float* __restrict__ key_W,
      const float* __restrict__ p_W1, const float* __restrict__ p_b1,
      const float* __restrict__ e_W, const float* __restrict__ e_b,
      const float* __restrict__ a_W, const float* __restrict__ a_b)
{
    extern __shared__ float sm[];
    float* sIn = sm;            // 64 x 132
    float* sW  = sm + SM_IN;    // 128 x 132
    __shared__ int sIdx[NROWS];

    const int tid = threadIdx.x;
    const bool qk = blockIdx.x < 400;
    const int row0 = (qk ? blockIdx.x : blockIdx.x - 400) * NROWS;

    if (tid < NROWS) sIdx[tid] = (qk ? Q : X)[row0 + tid];
    __syncthreads();

    {   // stage 64 embedding rows
        const float* emb = qk ? q_emb : x_emb;
        for (int i = tid; i < NROWS*32; i += 256) {
            int r = i >> 5, j = (i & 31) << 2;
            *(float4*)&sIn[r*IS + j] = *(const float4*)&emb[sIdx[r]*HH + j];
        }
    }

    if (qk) {
        // ---- logits + softmax:  (64 x 64), thread tile 4x4, cx16/ry16 ----
        for (int i = tid; i < CC*32; i += 256) {
            int r = i >> 5, j = (i & 31) << 2;
            *(float4*)&sW[r*IS + j] = *(const float4*)&key_W[r*HH + j];
        }
        __syncthreads();

        {
            const int cx = tid & 15, ry = tid >> 4;
            const int c0 = cx * 4;
            float acc[4][4];
            #pragma unroll
            for (int r = 0; r < 4; ++r)
                #pragma unroll
                for (int k = 0; k < 4; ++k) acc[r][k] = 0.f;
            #pragma unroll 2
            for (int j0 = 0; j0 < 128; j0 += 4) {
                float4 q[4], w[4];
                #pragma unroll
                for (int r = 0; r < 4; ++r)
                    q[r] = *(const float4*)&sIn[(ry*4 + r)*IS + j0];
                #pragma unroll
                for (int k = 0; k < 4; ++k)
                    w[k] = *(const float4*)&sW[(c0 + k)*IS + j0];
                #pragma unroll
                for (int r = 0; r < 4; ++r)
                    #pragma unroll
                    for (int k = 0; k < 4; ++k) {
                        acc[r][k] = fmaf(q[r].x, w[k].x, acc[r][k]);
                        acc[r][k] = fmaf(q[r].y, w[k].y, acc[r][k]);
                        acc[r][k] = fmaf(q[r].z, w[k].z, acc[r][k]);
                        acc[r][k] = fmaf(q[r].w, w[k].w, acc[r][k]);
                    }
            }
            // softmax across the 16-lane (cx) group
            #pragma unroll
            for (int r = 0; r < 4; ++r) {
                float mx = fmaxf(fmaxf(acc[r][0], acc[r][1]),
                                 fmaxf(acc[r][2], acc[r][3]));
                #pragma unroll
                for (int off = 8; off >= 1; off >>= 1)
                    mx = fmaxf(mx, __shfl_xor_sync(0xffffffffu, mx, off));
                float e0 = __expf(acc[r][0] - mx);
                float e1 = __expf(acc[r][1] - mx);
                float e2 = __expf(acc[r][2] - mx);
                float e3 = __expf(acc[r][3] - mx);
                float sum = (e0 + e1) + (e2 + e3);
                #pragma unroll
                for (int off = 8; off >= 1; off >>= 1)
                    sum += __shfl_xor_sync(0xffffffffu, sum, off);
                float inv = __frcp_rn(sum);
                *(float4*)&g_K[(row0 + ry*4 + r)*CC + c0] =
                    make_float4(e0*inv, e1*inv, e2*inv, e3*inv);
            }
        }
        __syncthreads();

        // ---- Qproj = Qe @ W1q.T + b1   (W1q = p_W1[:, :128]) ----
        for (int i = tid; i < HH*32; i += 256) {
            int r = i >> 5, j = (i & 31) << 2;
            *(float4*)&sW[r*IS + j] = *(const float4*)&p_W1[r*256 + j];
        }
        __syncthreads();
        {
            const int cx = tid & 31, ry = tid >> 5;
            const int c0 = cx * 4;
            float acc[8][4];
            gemm_8x4(sIn, sW, ry, c0, acc);
            float4 b = *(const float4*)&p_b1[c0];
            #pragma unroll
            for (int r = 0; r < 8; ++r) {
                int row = row0 + ry*8 + r;
                *(float4*)&g_Qp[row*HH + c0] =
                    make_float4(acc[r][0]+b.x, acc[r][1]+b.y,
                                acc[r][2]+b.z, acc[r][3]+b.w);
            }
        }
    } else {
        // ---- E = sigmoid(Xe@e_W.T + e_b) ----
        for (int i = tid; i < HH*32; i += 256) {
            int r = i >> 5, j = (i & 31) << 2;
            *(float4*)&sW[r*IS + j] = *(const float4*)&e_W[r*HH + j];
        }
        __syncthreads();
        const int cx = tid & 31, ry = tid >> 5;
        const int c0 = cx * 4;
        {
            float acc[8][4];
            gemm_8x4(sIn, sW, ry, c0, acc);
            float4 b = *(const float4*)&e_b[c0];
            #pragma unroll
            for (int r = 0; r < 8; ++r) {
                int row = row0 + ry*8 + r;
                *(float4*)&g_E[row*HH + c0] =
                    make_float4(fast_sigmoid(acc[r][0]+b.x),
                                fast_sigmoid(acc[r][1]+b.y),
                                fast_sigmoid(acc[r][2]+b.z),
                                fast_sigmoid(acc[r][3]+b.w));
            }
        }
        __syncthreads();
        // ---- A = tanh(Xe@a_W.T + a_b) ----
        for (int i = tid; i < HH*32; i += 256) {
            int r = i >> 5, j = (i & 31) << 2;
            *(float4*)&sW[r*IS + j] = *(const float4*)&a_W[r*HH + j];
        }
        __syncthreads();
        {
            float acc[8][4];
            gemm_8x4(sIn, sW, ry, c0, acc);
            float4 b = *(const float4*)&a_b[c0];
            #pragma unroll
            for (int r = 0; r < 8; ++r) {
                int row = row0 + ry*8 + r;
                *(float4*)&g_A[row*HH + c0] =
                    make_float4(fast_tanh(acc[r][0]+b.x),
                                fast_tanh(acc[r][1]+b.y),
                                fast_tanh(acc[r][2]+b.z),
                                fast_tanh(acc[r][3]+b.w));
            }
        }
    }
}

// ---------------- Kernel 2: the scan, fully parallel over (b,c,h) ------------
// warp = (b, 8 h's); lane: sub=lane>>2 picks h, g=lane&3 picks 16-wide c slice.
extern "C" __global__ void __launch_bounds__(256)
k_scan()
{
    const int tid  = threadIdx.x;
    const int b    = blockIdx.x >> 1;
    const int hblk = blockIdx.x & 1;
    const int wid  = tid >> 5;
    const int lane = tid & 31;
    const int sub  = lane >> 2;
    const int g    = lane & 3;
    const int h    = hblk*64 + wid*8 + sub;

    const float* Kp = g_K + b*LL*CC + g*16;
    const float* Ep = g_E + b*LL*HH + h;
    const float* Ap = g_A + b*LL*HH + h;
    float*       Rp = g_R + b*LL*HH + h;

    float m[16];
    #pragma unroll
    for (int j = 0; j < 16; ++j) m[j] = 0.f;

    #pragma unroll 2
    for (int t = 0; t < LL; ++t) {
        float k[16];
        *(float4*)&k[0]  = *(const float4*)(Kp + 0);
        *(float4*)&k[4]  = *(const float4*)(Kp + 4);
        *(float4*)&k[8]  = *(const float4*)(Kp + 8);
        *(float4*)&k[12] = *(const float4*)(Kp + 12);
        float e = *Ep;
        float a = *Ap;

        float s0 = 0.f, s1 = 0.f, s2 = 0.f, s3 = 0.f;
        #pragma unroll
        for (int j = 0; j < 4; ++j) {
            s0 = fmaf(k[j+ 0], m[j+ 0], s0);
            s1 = fmaf(k[j+ 4], m[j+ 4], s1);
            s2 = fmaf(k[j+ 8], m[j+ 8], s2);
            s3 = fmaf(k[j+12], m[j+12], s3);
        }
        float s = (s0 + s1) + (s2 + s3);
        s += __shfl_xor_sync(0xffffffffu, s, 1);
        s += __shfl_xor_sync(0xffffffffu, s, 2);
        if (g == 0) *Rp = s;

        #pragma unroll
        for (int j = 0; j < 16; ++j) {
            float tmp = fmaf(m[j], -e, a);     // a - m*e
            m[j] = fmaf(k[j], tmp, m[j]);      // m*(1-k*e) + k*a
        }
        Kp += CC; Ep += HH; Ap += HH; Rp += HH;
    }
}

// ---------------- Kernel 3: P = sigmoid(tanh(Qp + R@W1r.T) . pW2 + b2) -------
extern "C" __global__ void __launch_bounds__(256, 2)
k_out(const float* __restrict__ p_W1, const float* __restrict__ p_W2,
      const float* __restrict__ p_b2, float* __restrict__ out)
{
    extern __shared__ float sm[];
    float* sR = sm;             // 64 x 132
    float* sW = sm + SM_IN;     // 128 x 132 (W1r)
    __shared__ float sW2[HH];

    const int tid  = threadIdx.x;
    const int row0 = blockIdx.x * NROWS;

    if (tid < HH) sW2[tid] = p_W2[tid];
    for (int i = tid; i < NROWS*32; i += 256) {
        int r = i >> 5, j = (i & 31) << 2;
        *(float4*)&sR[r*IS + j] = *(const float4*)&g_R[(row0 + r)*HH + j];
    }
    for (int i = tid; i < HH*32; i += 256) {
        int r = i >> 5, j = (i & 31) << 2;
        *(float4*)&sW[r*IS + j] = *(const float4*)&p_W1[r*256 + 128 + j];
    }
    __syncthreads();

    const int cx = tid & 31, ry = tid >> 5;
    const int c0 = cx * 4;
    float acc[8][4];
    gemm_8x4(sR, sW, ry, c0, acc);

    const float b2 = __ldg(p_b2);
    float4 w2 = *(const float4*)&sW2[c0];

    #pragma unroll
    for (int r = 0; r < 8; ++r) {
        int row = row0 + ry*8 + r;
        float4 qp = *(const float4*)&g_Qp[row*HH + c0];
        float ps;
        ps  = fast_tanh(acc[r][0] + qp.x) * w2.x;
        ps += fast_tanh(acc[r][1] + qp.y) * w2.y;
        ps += fast_tanh(acc[r][2] + qp.z) * w2.z;
        ps += fast_tanh(acc[r][3] + qp.w) * w2.w;
        // full-warp reduction: all lanes in this warp share ry (same 8 rows)
        #pragma unroll
        for (int off = 16; off >= 1; off >>= 1)
            ps += __shfl_xor_sync(0xffffffffu, ps, off);
        if ((tid & 31) == 0)
            out[row] = fast_sigmoid(ps + b2);
    }
}

// ---------------- launch ----------------
extern "C" void kernel_launch(void* const* d_in, const int* in_sizes, int n_in,
                              void* d_out, int out_size)
{
    const int*   X     = (const int*)  d_in[0];
    const int*   Q     = (const int*)  d_in[1];
    const float* q_emb = (const float*)d_in[2];
    const float* x_emb = (const float*)d_in[3];
    const float* key_W = (const float*)d_in[4];
    const float* p_W1  = (const float*)d_in[5];
    const float* p_b1  = (const float*)d_in[6];
    const float* p_W2  = (const float*)d_in[7];
    const float* p_b2  = (const float*)d_in[8];
    const float* e_W   = (const float*)d_in[9];
    const float* e_b   = (const float*)d_in[10];
    const float* a_W   = (const float*)d_in[11];
    const float* a_b   = (const float*)d_in[12];
    float* out = (float*)d_out;

    static int configured = 0;
    if (!configured) {
        cudaFuncSetAttribute(k_pre, cudaFuncAttributeMaxDynamicSharedMemorySize, SMEM_BYTES);
        cudaFuncSetAttribute(k_out, cudaFuncAttributeMaxDynamicSharedMemorySize, SMEM_BYTES);
        configured = 1;
    }

    k_pre <<<800, 256, SMEM_BYTES>>>(X, Q, q_emb, x_emb, key_W,
                                     p_W1, p_b1, e_W, e_b, a_W, a_b);
    k_scan<<<BB*2, 256>>>();
    k_out <<<400, 256, SMEM_BYTES>>>(p_W1, p_W2, p_b2, out);
}

// round 3
// speedup vs baseline: 1.9627x; 1.5357x over previous
#include <cuda_runtime.h>

#define BB 128
#define LL 200
#define HH 128
#define CC 64

#define IS 130                    // smem row stride (floats): 2 mod 32 -> conflict-free LDS.64
#define NROWS 64
#define SM_IN  (NROWS*IS)         // 8320 floats
#define SM_W   (HH*IS)            // 16640 floats
#define SMEM_BYTES ((SM_IN + SM_W) * 4)   // 99840 B

typedef unsigned long long u64;

// ---- scratch (static device globals; no allocations) ----
__device__ float g_K [BB*LL*CC];
__device__ float g_Qp[BB*LL*HH];
__device__ float g_E [BB*LL*HH];
__device__ float g_A [BB*LL*HH];
__device__ float g_R [BB*LL*HH];

__device__ __forceinline__ u64 fma2(u64 a, u64 b, u64 c) {
    u64 d; asm("fma.rn.f32x2 %0, %1, %2, %3;" : "=l"(d) : "l"(a), "l"(b), "l"(c));
    return d;
}
__device__ __forceinline__ u64 pack2(float lo, float hi) {
    u64 d; asm("mov.b64 %0, {%1, %2};" : "=l"(d) : "f"(lo), "f"(hi));
    return d;
}
__device__ __forceinline__ float2 unpack2(u64 a) {
    float2 f; asm("mov.b64 {%0, %1}, %2;" : "=f"(f.x), "=f"(f.y) : "l"(a));
    return f;
}
__device__ __forceinline__ float fast_tanh(float x) {
    float y; asm("tanh.approx.f32 %0, %1;" : "=f"(y) : "f"(x)); return y;
}
__device__ __forceinline__ float fast_sigmoid(float x) {
    return 1.f / (1.f + __expf(-x));
}

// stage a [rows x 128] row-major gmem matrix into smem with stride IS (LDS.64-friendly)
__device__ __forceinline__ void stage(float* dst, const float* __restrict__ src,
                                      int rows, int tid, int srcStride)
{
    for (int i = tid; i < rows*32; i += 256) {
        int r = i >> 5, j = (i & 31) << 2;
        float4 v = *(const float4*)&src[r*srcStride + j];
        *(float2*)&dst[r*IS + j]     = make_float2(v.x, v.y);
        *(float2*)&dst[r*IS + j + 2] = make_float2(v.z, v.w);
    }
}

// 64x128 GEMM core: thread tile 8 rows x 4 cols (cols = cx + 32k), f32x2 over j-pairs.
// Result: acc[r][k] packed pairs; caller reduces lo+hi.
__device__ __forceinline__ void gemm2_8x4(const float* __restrict__ sIn,
                                          const float* __restrict__ sW,
                                          int ry, int cx, u64 acc[8][4])
{
    #pragma unroll
    for (int r = 0; r < 8; ++r)
        #pragma unroll
        for (int k = 0; k < 4; ++k) acc[r][k] = 0ull;

    const float* w0p = sW + (cx      )*IS;
    const float* w1p = sW + (cx + 32 )*IS;
    const float* w2p = sW + (cx + 64 )*IS;
    const float* w3p = sW + (cx + 96 )*IS;
    const float* qp  = sIn + ry*8*IS;

    #pragma unroll 8
    for (int j = 0; j < 128; j += 2) {
        u64 w0 = *(const u64*)(w0p + j);
        u64 w1 = *(const u64*)(w1p + j);
        u64 w2 = *(const u64*)(w2p + j);
        u64 w3 = *(const u64*)(w3p + j);
        #pragma unroll
        for (int r = 0; r < 8; ++r) {
            u64 q = *(const u64*)(qp + r*IS + j);
            acc[r][0] = fma2(q, w0, acc[r][0]);
            acc[r][1] = fma2(q, w1, acc[r][1]);
            acc[r][2] = fma2(q, w2, acc[r][2]);
            acc[r][3] = fma2(q, w3, acc[r][3]);
        }
    }
}

// ---------------- Kernel 1: fused precompute ---------------------------------
extern "C" __global__ void __launch_bounds__(256, 2)
k_pre(const int* __restrict__ X, const int* __restrict__ Q,
      const float* __restrict__ q_emb, const float* __restrict__ x_emb,
      const float* __restrict__ key_W,
      const float* __restrict__ p_W1, const float* __restrict__ p_b1,
      const float* __restrict__ e_W, const float* __restrict__ e_b,
      const float* __restrict__ a_W, const float* __restrict__ a_b)
{
    extern __shared__ float sm[];
    float* sIn = sm;
    float* sW  = sm + SM_IN;
    __shared__ int sIdx[NROWS];

    const int tid = threadIdx.x;
    const bool qk = blockIdx.x < 400;
    const int row0 = (qk ? blockIdx.x : blockIdx.x - 400) * NROWS;

    if (tid < NROWS) sIdx[tid] = (qk ? Q : X)[row0 + tid];
    __syncthreads();

    {   // stage 64 embedding rows (gathered)
        const float* emb = qk ? q_emb : x_emb;
        for (int i = tid; i < NROWS*32; i += 256) {
            int r = i >> 5, j = (i & 31) << 2;
            float4 v = *(const float4*)&emb[sIdx[r]*HH + j];
            *(float2*)&sIn[r*IS + j]     = make_float2(v.x, v.y);
            *(float2*)&sIn[r*IS + j + 2] = make_float2(v.z, v.w);
        }
    }

    if (qk) {
        // ---- logits + softmax: 64x64, thread tile 4x4 (cols cx16+16k) ----
        stage(sW, key_W, CC, tid, HH);
        __syncthreads();
        {
            const int cx = tid & 15;          // 16 col lanes
            const int ry = tid >> 4;          // 16 row groups x 4 rows
            u64 acc[4][4];
            #pragma unroll
            for (int r = 0; r < 4; ++r)
                #pragma unroll
                for (int k = 0; k < 4; ++k) acc[r][k] = 0ull;

            const float* qp = sIn + ry*4*IS;
            #pragma unroll 8
            for (int j = 0; j < 128; j += 2) {
                u64 w0 = *(const u64*)(sW + (cx      )*IS + j);
                u64 w1 = *(const u64*)(sW + (cx + 16 )*IS + j);
                u64 w2 = *(const u64*)(sW + (cx + 32 )*IS + j);
                u64 w3 = *(const u64*)(sW + (cx + 48 )*IS + j);
                #pragma unroll
                for (int r = 0; r < 4; ++r) {
                    u64 q = *(const u64*)(qp + r*IS + j);
                    acc[r][0] = fma2(q, w0, acc[r][0]);
                    acc[r][1] = fma2(q, w1, acc[r][1]);
                    acc[r][2] = fma2(q, w2, acc[r][2]);
                    acc[r][3] = fma2(q, w3, acc[r][3]);
                }
            }
            #pragma unroll
            for (int r = 0; r < 4; ++r) {
                float v[4];
                #pragma unroll
                for (int k = 0; k < 4; ++k) {
                    float2 f = unpack2(acc[r][k]);
                    v[k] = f.x + f.y;
                }
                float mx = fmaxf(fmaxf(v[0], v[1]), fmaxf(v[2], v[3]));
                #pragma unroll
                for (int off = 8; off >= 1; off >>= 1)
                    mx = fmaxf(mx, __shfl_xor_sync(0xffffffffu, mx, off));
                float e0 = __expf(v[0]-mx), e1 = __expf(v[1]-mx);
                float e2 = __expf(v[2]-mx), e3 = __expf(v[3]-mx);
                float sum = (e0+e1) + (e2+e3);
                #pragma unroll
                for (int off = 8; off >= 1; off >>= 1)
                    sum += __shfl_xor_sync(0xffffffffu, sum, off);
                float inv = __frcp_rn(sum);
                float* o = &g_K[(row0 + ry*4 + r)*CC + cx];
                o[0]  = e0*inv; o[16] = e1*inv; o[32] = e2*inv; o[48] = e3*inv;
            }
        }
        __syncthreads();

        // ---- Qproj = Qe @ W1q.T + b1 ----
        stage(sW, p_W1, HH, tid, 256);        // W1q = p_W1[:, :128]
        __syncthreads();
        {
            const int cx = tid & 31, ry = tid >> 5;
            u64 acc[8][4];
            gemm2_8x4(sIn, sW, ry, cx, acc);
            float b[4] = { p_b1[cx], p_b1[cx+32], p_b1[cx+64], p_b1[cx+96] };
            #pragma unroll
            for (int r = 0; r < 8; ++r) {
                float* o = &g_Qp[(row0 + ry*8 + r)*HH + cx];
                #pragma unroll
                for (int k = 0; k < 4; ++k) {
                    float2 f = unpack2(acc[r][k]);
                    o[k*32] = f.x + f.y + b[k];
                }
            }
        }
    } else {
        const int cx = tid & 31, ry = tid >> 5;
        // ---- E = sigmoid(Xe@e_W.T + e_b) ----
        stage(sW, e_W, HH, tid, HH);
        __syncthreads();
        {
            u64 acc[8][4];
            gemm2_8x4(sIn, sW, ry, cx, acc);
            float b[4] = { e_b[cx], e_b[cx+32], e_b[cx+64], e_b[cx+96] };
            #pragma unroll
            for (int r = 0; r < 8; ++r) {
                float* o = &g_E[(row0 + ry*8 + r)*HH + cx];
                #pragma unroll
                for (int k = 0; k < 4; ++k) {
                    float2 f = unpack2(acc[r][k]);
                    o[k*32] = fast_sigmoid(f.x + f.y + b[k]);
                }
            }
        }
        __syncthreads();
        // ---- A = tanh(Xe@a_W.T + a_b) ----
        stage(sW, a_W, HH, tid, HH);
        __syncthreads();
        {
            u64 acc[8][4];
            gemm2_8x4(sIn, sW, ry, cx, acc);
            float b[4] = { a_b[cx], a_b[cx+32], a_b[cx+64], a_b[cx+96] };
            #pragma unroll
            for (int r = 0; r < 8; ++r) {
                float* o = &g_A[(row0 + ry*8 + r)*HH + cx];
                #pragma unroll
                for (int k = 0; k < 4; ++k) {
                    float2 f = unpack2(acc[r][k]);
                    o[k*32] = fast_tanh(f.x + f.y + b[k]);
                }
            }
        }
    }
}

// ---------------- Kernel 2: the scan ----------------------------------------
// 512 blocks x 128 thr. block = (b, 32 h's); warp = 8 h; lane: sub=h, g=c-slice.
extern "C" __global__ void __launch_bounds__(128)
k_scan()
{
    const int tid  = threadIdx.x;
    const int b    = blockIdx.x >> 2;
    const int hblk = blockIdx.x & 3;
    const int wid  = tid >> 5;
    const int lane = tid & 31;
    const int sub  = lane >> 2;
    const int g    = lane & 3;
    const int h    = hblk*32 + wid*8 + sub;

    const float* Kb = g_K + b*LL*CC + g*16;
    const float* Eb = g_E + b*LL*HH + h;
    const float* Ab = g_A + b*LL*HH + h;
    float*       Rb = g_R + b*LL*HH + h;

    u64 m2[8];
    #pragma unroll
    for (int i = 0; i < 8; ++i) m2[i] = 0ull;

    // prefetch t = 0
    u64 kc[8]; float ec, ac;
    {
        const ulonglong2* p = (const ulonglong2*)Kb;
        ulonglong2 a0 = p[0], a1 = p[1], a2 = p[2], a3 = p[3];
        kc[0]=a0.x; kc[1]=a0.y; kc[2]=a1.x; kc[3]=a1.y;
        kc[4]=a2.x; kc[5]=a2.y; kc[6]=a3.x; kc[7]=a3.y;
        ec = Eb[0]; ac = Ab[0];
    }

    #pragma unroll 2
    for (int t = 0; t < LL; ++t) {
        // prefetch t+1 (clamped)
        const int tn = (t + 1 < LL) ? t + 1 : t;
        u64 kn[8]; float en, an;
        {
            const ulonglong2* p = (const ulonglong2*)(Kb + tn*CC);
            ulonglong2 a0 = p[0], a1 = p[1], a2 = p[2], a3 = p[3];
            kn[0]=a0.x; kn[1]=a0.y; kn[2]=a1.x; kn[3]=a1.y;
            kn[4]=a2.x; kn[5]=a2.y; kn[6]=a3.x; kn[7]=a3.y;
            en = Eb[tn*HH]; an = Ab[tn*HH];
        }

        // dot: R = sum_c k*m (two chains, depth 4)
        u64 sA = 0ull, sB = 0ull;
        #pragma unroll
        for (int i = 0; i < 4; ++i) {
            sA = fma2(kc[i],   m2[i],   sA);
            sB = fma2(kc[i+4], m2[i+4], sB);
        }
        float2 fa = unpack2(sA), fb = unpack2(sB);
        float s = (fa.x + fa.y) + (fb.x + fb.y);
        s += __shfl_xor_sync(0xffffffffu, s, 1);
        s += __shfl_xor_sync(0xffffffffu, s, 2);
        if (g == 0) Rb[t*HH] = s;

        // update: m = m*(1 - k*e) + k*a = m + k*(a - m*e)
        u64 nee = pack2(-ec, -ec);
        u64 aa2 = pack2( ac,  ac);
        #pragma unroll
        for (int i = 0; i < 8; ++i)
            m2[i] = fma2(kc[i], fma2(m2[i], nee, aa2), m2[i]);

        #pragma unroll
        for (int i = 0; i < 8; ++i) kc[i] = kn[i];
        ec = en; ac = an;
    }
}

// ---------------- Kernel 3: P = sigmoid(tanh(Qp + R@W1r.T) . pW2 + b2) -------
extern "C" __global__ void __launch_bounds__(256, 2)
k_out(const float* __restrict__ p_W1, const float* __restrict__ p_W2,
      const float* __restrict__ p_b2, float* __restrict__ out)
{
    extern __shared__ float sm[];
    float* sR = sm;
    float* sW = sm + SM_IN;
    __shared__ float sW2[HH];

    const int tid  = threadIdx.x;
    const int row0 = blockIdx.x * NROWS;

    if (tid < HH) sW2[tid] = p_W2[tid];
    for (int i = tid; i < NROWS*32; i += 256) {
        int r = i >> 5, j = (i & 31) << 2;
        float4 v = *(const float4*)&g_R[(row0 + r)*HH + j];
        *(float2*)&sR[r*IS + j]     = make_float2(v.x, v.y);
        *(float2*)&sR[r*IS + j + 2] = make_float2(v.z, v.w);
    }
    // W1r = p_W1[:, 128:]
    for (int i = tid; i < HH*32; i += 256) {
        int r = i >> 5, j = (i & 31) << 2;
        float4 v = *(const float4*)&p_W1[r*256 + 128 + j];
        *(float2*)&sW[r*IS + j]     = make_float2(v.x, v.y);
        *(float2*)&sW[r*IS + j + 2] = make_float2(v.z, v.w);
    }
    __syncthreads();

    const int cx = tid & 31, ry = tid >> 5;
    u64 acc[8][4];
    gemm2_8x4(sR, sW, ry, cx, acc);

    const float b2 = __ldg(p_b2);
    float w2[4] = { sW2[cx], sW2[cx+32], sW2[cx+64], sW2[cx+96] };

    #pragma unroll
    for (int r = 0; r < 8; ++r) {
        int row = row0 + ry*8 + r;
        const float* qp = &g_Qp[row*HH + cx];
        float ps = 0.f;
        #pragma unroll
        for (int k = 0; k < 4; ++k) {
            float2 f = unpack2(acc[r][k]);
            ps = fmaf(fast_tanh(f.x + f.y + qp[k*32]), w2[k], ps);
        }
        #pragma unroll
        for (int off = 16; off >= 1; off >>= 1)
            ps += __shfl_xor_sync(0xffffffffu, ps, off);
        if ((tid & 31) == 0)
            out[row] = fast_sigmoid(ps + b2);
    }
}

// ---------------- launch ----------------
extern "C" void kernel_launch(void* const* d_in, const int* in_sizes, int n_in,
                              void* d_out, int out_size)
{
    const int*   X     = (const int*)  d_in[0];
    const int*   Q     = (const int*)  d_in[1];
    const float* q_emb = (const float*)d_in[2];
    const float* x_emb = (const float*)d_in[3];
    const float* key_W = (const float*)d_in[4];
    const float* p_W1  = (const float*)d_in[5];
    const float* p_b1  = (const float*)d_in[6];
    const float* p_W2  = (const float*)d_in[7];
    const float* p_b2  = (const float*)d_in[8];
    const float* e_W   = (const float*)d_in[9];
    const float* e_b   = (const float*)d_in[10];
    const float* a_W   = (const float*)d_in[11];
    const float* a_b   = (const float*)d_in[12];
    float* out = (float*)d_out;

    static int configured = 0;
    if (!configured) {
        cudaFuncSetAttribute(k_pre, cudaFuncAttributeMaxDynamicSharedMemorySize, SMEM_BYTES);
        cudaFuncSetAttribute(k_out, cudaFuncAttributeMaxDynamicSharedMemorySize, SMEM_BYTES);
        configured = 1;
    }

    k_pre <<<800, 256, SMEM_BYTES>>>(X, Q, q_emb, x_emb, key_W,
                                     p_W1, p_b1, e_W, e_b, a_W, a_b);
    k_scan<<<BB*4, 128>>>();
    k_out <<<400, 256, SMEM_BYTES>>>(p_W1, p_W2, p_b2, out);
}

// round 4
// speedup vs baseline: 1.9664x; 1.0019x over previous
#include <cuda_runtime.h>

#define BB 128
#define LL 200
#define HH 128
#define CC 64

#define IS 132                    // smem stride (floats): 4 mod 32 -> conflict-free LDS.128
#define NROWS 64
#define SM_IN  (NROWS*IS)
#define SM_W   (HH*IS)
#define SMEM_BYTES ((SM_IN + SM_W) * 4)          // 101376 B

#define FUSED_SMEM ((LL*IS + HH*IS) * 4)         // 173184 B

typedef unsigned long long u64;

// ---- scratch (static device globals; no allocations) ----
__device__ float g_K [BB*LL*CC];
__device__ float g_Qp[BB*LL*HH];
__device__ float g_E [BB*LL*HH];
__device__ float g_A [BB*LL*HH];

__device__ __forceinline__ u64 fma2(u64 a, u64 b, u64 c) {
    u64 d; asm("fma.rn.f32x2 %0, %1, %2, %3;" : "=l"(d) : "l"(a), "l"(b), "l"(c));
    return d;
}
__device__ __forceinline__ u64 pack2(float lo, float hi) {
    u64 d; asm("mov.b64 %0, {%1, %2};" : "=l"(d) : "f"(lo), "f"(hi));
    return d;
}
__device__ __forceinline__ float2 unpack2(u64 a) {
    float2 f; asm("mov.b64 {%0, %1}, %2;" : "=f"(f.x), "=f"(f.y) : "l"(a));
    return f;
}
__device__ __forceinline__ float fast_tanh(float x) {
    float y; asm("tanh.approx.f32 %0, %1;" : "=f"(y) : "f"(x)); return y;
}
__device__ __forceinline__ float fast_sigmoid(float x) {
    return 1.f / (1.f + __expf(-x));
}

// stage a [rows x 128] row-major gmem matrix into smem with stride IS
__device__ __forceinline__ void stage(float* dst, const float* __restrict__ src,
                                      int rows, int tid, int nthr, int srcStride)
{
    for (int i = tid; i < rows*32; i += nthr) {
        int r = i >> 5, j = (i & 31) << 2;
        *(float4*)&dst[r*IS + j] = *(const float4*)&src[r*srcStride + j];
    }
}

// 64x128 GEMM core: thread tile 8 rows x 4 cols (cols = cx + 32k).
// Inner step: 4 j's via LDS.128 (ulonglong2 -> two f32x2 fma per load).
__device__ __forceinline__ void gemm4_8x4(const float* __restrict__ sIn,
                                          const float* __restrict__ sW,
                                          int ry, int cx, u64 acc[8][4])
{
    #pragma unroll
    for (int r = 0; r < 8; ++r)
        #pragma unroll
        for (int k = 0; k < 4; ++k) acc[r][k] = 0ull;

    const float* w0p = sW + (cx      )*IS;
    const float* w1p = sW + (cx + 32 )*IS;
    const float* w2p = sW + (cx + 64 )*IS;
    const float* w3p = sW + (cx + 96 )*IS;
    const float* qp  = sIn + ry*8*IS;

    #pragma unroll 4
    for (int j = 0; j < 128; j += 4) {
        ulonglong2 w0 = *(const ulonglong2*)(w0p + j);
        ulonglong2 w1 = *(const ulonglong2*)(w1p + j);
        ulonglong2 w2 = *(const ulonglong2*)(w2p + j);
        ulonglong2 w3 = *(const ulonglong2*)(w3p + j);
        #pragma unroll
        for (int r = 0; r < 8; ++r) {
            ulonglong2 q = *(const ulonglong2*)(qp + r*IS + j);
            acc[r][0] = fma2(q.x, w0.x, acc[r][0]);
            acc[r][1] = fma2(q.x, w1.x, acc[r][1]);
            acc[r][2] = fma2(q.x, w2.x, acc[r][2]);
            acc[r][3] = fma2(q.x, w3.x, acc[r][3]);
            acc[r][0] = fma2(q.y, w0.y, acc[r][0]);
            acc[r][1] = fma2(q.y, w1.y, acc[r][1]);
            acc[r][2] = fma2(q.y, w2.y, acc[r][2]);
            acc[r][3] = fma2(q.y, w3.y, acc[r][3]);
        }
    }
}

// ---------------- Kernel 1: fused precompute ---------------------------------
extern "C" __global__ void __launch_bounds__(256, 2)
k_pre(const int* __restrict__ X, const int* __restrict__ Q,
      const float* __restrict__ q_emb, const float* __restrict__ x_emb,
      const float* __restrict__ key_W,
      const float* __restrict__ p_W1, const float* __restrict__ p_b1,
      const float* __restrict__ e_W, const float* __restrict__ e_b,
      const float* __restrict__ a_W, const float* __restrict__ a_b)
{
    extern __shared__ float sm[];
    float* sIn = sm;
    float* sW  = sm + SM_IN;
    __shared__ int sIdx[NROWS];

    const int tid = threadIdx.x;
    const bool qk = blockIdx.x < 400;
    const int row0 = (qk ? blockIdx.x : blockIdx.x - 400) * NROWS;

    if (tid < NROWS) sIdx[tid] = (qk ? Q : X)[row0 + tid];
    __syncthreads();

    {   // stage 64 gathered embedding rows
        const float* emb = qk ? q_emb : x_emb;
        for (int i = tid; i < NROWS*32; i += 256) {
            int r = i >> 5, j = (i & 31) << 2;
            *(float4*)&sIn[r*IS + j] = *(const float4*)&emb[sIdx[r]*HH + j];
        }
    }

    if (qk) {
        // ---- logits + softmax: 64x64, tile 4x4 (cols cx + 16k) ----
        stage(sW, key_W, CC, tid, 256, HH);
        __syncthreads();
        {
            const int cx = tid & 15;
            const int ry = tid >> 4;
            u64 acc[4][4];
            #pragma unroll
            for (int r = 0; r < 4; ++r)
                #pragma unroll
                for (int k = 0; k < 4; ++k) acc[r][k] = 0ull;

            const float* w0p = sW + (cx      )*IS;
            const float* w1p = sW + (cx + 16 )*IS;
            const float* w2p = sW + (cx + 32 )*IS;
            const float* w3p = sW + (cx + 48 )*IS;
            const float* qp  = sIn + ry*4*IS;

            #pragma unroll 4
            for (int j = 0; j < 128; j += 4) {
                ulonglong2 w0 = *(const ulonglong2*)(w0p + j);
                ulonglong2 w1 = *(const ulonglong2*)(w1p + j);
                ulonglong2 w2 = *(const ulonglong2*)(w2p + j);
                ulonglong2 w3 = *(const ulonglong2*)(w3p + j);
                #pragma unroll
                for (int r = 0; r < 4; ++r) {
                    ulonglong2 q = *(const ulonglong2*)(qp + r*IS + j);
                    acc[r][0] = fma2(q.x, w0.x, acc[r][0]);
                    acc[r][1] = fma2(q.x, w1.x, acc[r][1]);
                    acc[r][2] = fma2(q.x, w2.x, acc[r][2]);
                    acc[r][3] = fma2(q.x, w3.x, acc[r][3]);
                    acc[r][0] = fma2(q.y, w0.y, acc[r][0]);
                    acc[r][1] = fma2(q.y, w1.y, acc[r][1]);
                    acc[r][2] = fma2(q.y, w2.y, acc[r][2]);
                    acc[r][3] = fma2(q.y, w3.y, acc[r][3]);
                }
            }
            #pragma unroll
            for (int r = 0; r < 4; ++r) {
                float v[4];
                #pragma unroll
                for (int k = 0; k < 4; ++k) {
                    float2 f = unpack2(acc[r][k]);
                    v[k] = f.x + f.y;
                }
                float mx = fmaxf(fmaxf(v[0], v[1]), fmaxf(v[2], v[3]));
                #pragma unroll
                for (int off = 8; off >= 1; off >>= 1)
                    mx = fmaxf(mx, __shfl_xor_sync(0xffffffffu, mx, off));
                float e0 = __expf(v[0]-mx), e1 = __expf(v[1]-mx);
                float e2 = __expf(v[2]-mx), e3 = __expf(v[3]-mx);
                float sum = (e0+e1) + (e2+e3);
                #pragma unroll
                for (int off = 8; off >= 1; off >>= 1)
                    sum += __shfl_xor_sync(0xffffffffu, sum, off);
                float inv = __frcp_rn(sum);
                float* o = &g_K[(row0 + ry*4 + r)*CC + cx];
                o[0]  = e0*inv; o[16] = e1*inv; o[32] = e2*inv; o[48] = e3*inv;
            }
        }
        __syncthreads();

        // ---- Qproj = Qe @ W1q.T + b1 ----
        stage(sW, p_W1, HH, tid, 256, 256);     // W1q = p_W1[:, :128]
        __syncthreads();
        {
            const int cx = tid & 31, ry = tid >> 5;
            u64 acc[8][4];
            gemm4_8x4(sIn, sW, ry, cx, acc);
            float b[4] = { p_b1[cx], p_b1[cx+32], p_b1[cx+64], p_b1[cx+96] };
            #pragma unroll
            for (int r = 0; r < 8; ++r) {
                float* o = &g_Qp[(row0 + ry*8 + r)*HH + cx];
                #pragma unroll
                for (int k = 0; k < 4; ++k) {
                    float2 f = unpack2(acc[r][k]);
                    o[k*32] = f.x + f.y + b[k];
                }
            }
        }
    } else {
        const int cx = tid & 31, ry = tid >> 5;
        // ---- E = sigmoid(Xe@e_W.T + e_b) ----
        stage(sW, e_W, HH, tid, 256, HH);
        __syncthreads();
        {
            u64 acc[8][4];
            gemm4_8x4(sIn, sW, ry, cx, acc);
            float b[4] = { e_b[cx], e_b[cx+32], e_b[cx+64], e_b[cx+96] };
            #pragma unroll
            for (int r = 0; r < 8; ++r) {
                float* o = &g_E[(row0 + ry*8 + r)*HH + cx];
                #pragma unroll
                for (int k = 0; k < 4; ++k) {
                    float2 f = unpack2(acc[r][k]);
                    o[k*32] = fast_sigmoid(f.x + f.y + b[k]);
                }
            }
        }
        __syncthreads();
        // ---- A = tanh(Xe@a_W.T + a_b) ----
        stage(sW, a_W, HH, tid, 256, HH);
        __syncthreads();
        {
            u64 acc[8][4];
            gemm4_8x4(sIn, sW, ry, cx, acc);
            float b[4] = { a_b[cx], a_b[cx+32], a_b[cx+64], a_b[cx+96] };
            #pragma unroll
            for (int r = 0; r < 8; ++r) {
                float* o = &g_A[(row0 + ry*8 + r)*HH + cx];
                #pragma unroll
                for (int k = 0; k < 4; ++k) {
                    float2 f = unpack2(acc[r][k]);
                    o[k*32] = fast_tanh(f.x + f.y + b[k]);
                }
            }
        }
    }
}

// ---------------- Kernel 2: fused scan + output ------------------------------
// 128 blocks (one per b) x 512 threads (16 warps = all 128 h).
// Phase 1: scan over t, R written to smem. Phase 2: in-block output GEMM.
extern "C" __global__ void __launch_bounds__(512, 1)
k_scan_out(const float* __restrict__ p_W1, const float* __restrict__ p_W2,
           const float* __restrict__ p_b2, float* __restrict__ out)
{
    extern __shared__ float sm[];
    float* sR = sm;                 // 200 x 132 (R[t, h])
    float* sW = sm + LL*IS;         // 128 x 132 (W1r)
    __shared__ float sW2[HH];

    const int tid  = threadIdx.x;
    const int b    = blockIdx.x;
    const int wid  = tid >> 5;
    const int lane = tid & 31;
    const int sub  = lane >> 2;
    const int g    = lane & 3;
    const int h    = wid*8 + sub;

    if (tid < HH) sW2[tid] = p_W2[tid];

    // ---- Phase 1: scan ----
    {
        const float* Kb = g_K + b*LL*CC + g*16;
        const float* Eb = g_E + b*LL*HH + h;
        const float* Ab = g_A + b*LL*HH + h;

        u64 m2[8];
        #pragma unroll
        for (int i = 0; i < 8; ++i) m2[i] = 0ull;

        u64 kc[8]; float ec, ac;
        {
            const ulonglong2* p = (const ulonglong2*)Kb;
            ulonglong2 a0 = p[0], a1 = p[1], a2 = p[2], a3 = p[3];
            kc[0]=a0.x; kc[1]=a0.y; kc[2]=a1.x; kc[3]=a1.y;
            kc[4]=a2.x; kc[5]=a2.y; kc[6]=a3.x; kc[7]=a3.y;
            ec = Eb[0]; ac = Ab[0];
        }

        #pragma unroll 2
        for (int t = 0; t < LL; ++t) {
            const int tn = (t + 1 < LL) ? t + 1 : t;
            u64 kn[8]; float en, an;
            {
                const ulonglong2* p = (const ulonglong2*)(Kb + tn*CC);
                ulonglong2 a0 = p[0], a1 = p[1], a2 = p[2], a3 = p[3];
                kn[0]=a0.x; kn[1]=a0.y; kn[2]=a1.x; kn[3]=a1.y;
                kn[4]=a2.x; kn[5]=a2.y; kn[6]=a3.x; kn[7]=a3.y;
                en = Eb[tn*HH]; an = Ab[tn*HH];
            }

            u64 sA = 0ull, sB = 0ull;
            #pragma unroll
            for (int i = 0; i < 4; ++i) {
                sA = fma2(kc[i],   m2[i],   sA);
                sB = fma2(kc[i+4], m2[i+4], sB);
            }
            float2 fa = unpack2(sA), fb = unpack2(sB);
            float s = (fa.x + fa.y) + (fb.x + fb.y);
            s += __shfl_xor_sync(0xffffffffu, s, 1);
            s += __shfl_xor_sync(0xffffffffu, s, 2);
            if (g == 0) sR[t*IS + h] = s;

            u64 nee = pack2(-ec, -ec);
            u64 aa2 = pack2( ac,  ac);
            #pragma unroll
            for (int i = 0; i < 8; ++i)
                m2[i] = fma2(kc[i], fma2(m2[i], nee, aa2), m2[i]);

            #pragma unroll
            for (int i = 0; i < 8; ++i) kc[i] = kn[i];
            ec = en; ac = an;
        }
    }

    // stage W1r = p_W1[:, 128:] while R finishes
    stage(sW, p_W1 + 128, HH, tid, 512, 256);
    __syncthreads();

    // ---- Phase 2: P[b, t] = sigmoid(tanh(Qp + R@W1r.T) . w2 + b2) ----
    const int cx = tid & 31;        // col = cx + 32k
    const int ry = tid >> 5;        // 16 row groups x 4 rows per pass
    const float b2v = __ldg(p_b2);
    float w2c[4] = { sW2[cx], sW2[cx+32], sW2[cx+64], sW2[cx+96] };

    const float* w0p = sW + (cx      )*IS;
    const float* w1p = sW + (cx + 32 )*IS;
    const float* w2p = sW + (cx + 64 )*IS;
    const float* w3p = sW + (cx + 96 )*IS;

    #pragma unroll
    for (int pass = 0; pass < 4; ++pass) {
        const int rb = pass*64 + ry*4;           // first row (t) of this group
        u64 acc[4][4];
        #pragma unroll
        for (int r = 0; r < 4; ++r)
            #pragma unroll
            for (int k = 0; k < 4; ++k) acc[r][k] = 0ull;

        int rc[4];
        #pragma unroll
        for (int r = 0; r < 4; ++r) rc[r] = (rb + r < LL) ? rb + r : LL - 1;

        #pragma unroll 4
        for (int j = 0; j < 128; j += 4) {
            ulonglong2 w0 = *(const ulonglong2*)(w0p + j);
            ulonglong2 w1 = *(const ulonglong2*)(w1p + j);
            ulonglong2 w2 = *(const ulonglong2*)(w2p + j);
            ulonglong2 w3 = *(const ulonglong2*)(w3p + j);
            #pragma unroll
            for (int r = 0; r < 4; ++r) {
                ulonglong2 q = *(const ulonglong2*)(sR + rc[r]*IS + j);
                acc[r][0] = fma2(q.x, w0.x, acc[r][0]);
                acc[r][1] = fma2(q.x, w1.x, acc[r][1]);
                acc[r][2] = fma2(q.x, w2.x, acc[r][2]);
                acc[r][3] = fma2(q.x, w3.x, acc[r][3]);
                acc[r][0] = fma2(q.y, w0.y, acc[r][0]);
                acc[r][1] = fma2(q.y, w1.y, acc[r][1]);
                acc[r][2] = fma2(q.y, w2.y, acc[r][2]);
                acc[r][3] = fma2(q.y, w3.y, acc[r][3]);
            }
        }

        #pragma unroll
        for (int r = 0; r < 4; ++r) {
            const float* qp = &g_Qp[(b*LL + rc[r])*HH + cx];
            float ps = 0.f;
            #pragma unroll
            for (int k = 0; k < 4; ++k) {
                float2 f = unpack2(acc[r][k]);
                ps = fmaf(fast_tanh(f.x + f.y + qp[k*32]), w2c[k], ps);
            }
            #pragma unroll
            for (int off = 16; off >= 1; off >>= 1)
                ps += __shfl_xor_sync(0xffffffffu, ps, off);
            if (lane == 0 && rb + r < LL)
                out[b*LL + rb + r] = fast_sigmoid(ps + b2v);
        }
    }
}

// ---------------- launch ----------------
extern "C" void kernel_launch(void* const* d_in, const int* in_sizes, int n_in,
                              void* d_out, int out_size)
{
    const int*   X     = (const int*)  d_in[0];
    const int*   Q     = (const int*)  d_in[1];
    const float* q_emb = (const float*)d_in[2];
    const float* x_emb = (const float*)d_in[3];
    const float* key_W = (const float*)d_in[4];
    const float* p_W1  = (const float*)d_in[5];
    const float* p_b1  = (const float*)d_in[6];
    const float* p_W2  = (const float*)d_in[7];
    const float* p_b2  = (const float*)d_in[8];
    const float* e_W   = (const float*)d_in[9];
    const float* e_b   = (const float*)d_in[10];
    const float* a_W   = (const float*)d_in[11];
    const float* a_b   = (const float*)d_in[12];
    float* out = (float*)d_out;

    static int configured = 0;
    if (!configured) {
        cudaFuncSetAttribute(k_pre,      cudaFuncAttributeMaxDynamicSharedMemorySize, SMEM_BYTES);
        cudaFuncSetAttribute(k_scan_out, cudaFuncAttributeMaxDynamicSharedMemorySize, FUSED_SMEM);
        configured = 1;
    }

    k_pre     <<<800, 256, SMEM_BYTES>>>(X, Q, q_emb, x_emb, key_W,
                                         p_W1, p_b1, e_W, e_b, a_W, a_b);
    k_scan_out<<<BB, 512, FUSED_SMEM>>>(p_W1, p_W2, p_b2, out);
}